// round 4
// baseline (speedup 1.0000x reference)
#include <cuda_runtime.h>
#include <cuda_fp16.h>
#include <math.h>

#define T_    128
#define BSZ   1024
#define IN_   75
#define H_    128
#define G4_   512
#define OUT_  256
#define MDEC  (128*75)
#define EPS_  1e-5f
#define NBLK  128
#define STHR  256

// ---------------- device scratch ----------------
__device__ float  g_xTm [(size_t)T_*IN_*BSZ];
__device__ float  g_XT  [(size_t)T_*G4_*BSZ];
__device__ float  g_hs0T[(size_t)T_*H_*BSZ];
__device__ float  g_hs1T[(size_t)T_*H_*BSZ];
__device__ __half g_h16 [(size_t)2*H_*BSZ];    // ping-pong fp16 recurrent h
__device__ float  g_xsA [(size_t)T_*G4_];
__device__ float  g_xsB [(size_t)T_*G4_];
__device__ float  g_embT[(size_t)OUT_*BSZ];
__device__ unsigned g_barArr;

__global__ void reset_bar_k() { g_barArr = 0u; }

__device__ __forceinline__ float tanh_fast(float x) {
    float y; asm("tanh.approx.f32 %0, %1;" : "=f"(y) : "f"(x)); return y;
}
__device__ __forceinline__ float sigm(float x) {
    return fmaf(0.5f, tanh_fast(0.5f * x), 0.5f);
}

// ---------------- transpose sequences (B,T,IN) -> (T,IN,B) ----------------
__global__ __launch_bounds__(256) void transpose_seq(const float* __restrict__ seq,
                                                     float* __restrict__ xTm)
{
    int t  = blockIdx.y;
    int b0 = blockIdx.x * 128;
    __shared__ float sm[128 * 77];
    int tid = threadIdx.x;
    for (int i = tid; i < 128 * IN_; i += 256) {
        int bl = i / IN_, k = i % IN_;
        sm[bl * 77 + k] = seq[(size_t)(b0 + bl) * (T_ * IN_) + (size_t)t * IN_ + k];
    }
    __syncthreads();
    for (int i = tid; i < IN_ * 128; i += 256) {
        int k = i / 128, bl = i % 128;
        xTm[(size_t)t * IN_ * BSZ + (size_t)k * BSZ + b0 + bl] = sm[bl * 77 + k];
    }
}

// ---------------- TN SGEMM 128x128 tile, BK=16, 8x8 micro-tile ----------------
// C[n][b] = sum_k W[k][n] * A[k][b].  N,Bd multiples of 128 (K arbitrary).
__global__ __launch_bounds__(256) void tn_gemm128(const float* __restrict__ W,
                                                  const float* __restrict__ A,
                                                  float* __restrict__ C,
                                                  int K, int N, int Bd,
                                                  long long strideA, long long strideC,
                                                  const float* __restrict__ bias_n,
                                                  const float* __restrict__ bias_b)
{
    A += (size_t)blockIdx.z * strideA;
    C += (size_t)blockIdx.z * strideC;
    const int n0 = blockIdx.y * 128;
    const int b0 = blockIdx.x * 128;

    __shared__ float Ws[16][128];
    __shared__ float As[16][128];

    const int tid = threadIdx.x;
    const int lr = tid / 32;          // loader row (and +8)
    const int lc = (tid % 32) * 4;    // loader col
    const int tx = tid % 16;          // batch dir
    const int ty = tid / 16;          // n dir

    float acc[8][8];
#pragma unroll
    for (int i = 0; i < 8; i++)
#pragma unroll
        for (int jj = 0; jj < 8; jj++) acc[i][jj] = 0.f;

    for (int k0 = 0; k0 < K; k0 += 16) {
#pragma unroll
        for (int rr = 0; rr < 2; rr++) {
            const int krow = k0 + lr + rr * 8;
            float4 wv = make_float4(0.f, 0.f, 0.f, 0.f);
            float4 av = make_float4(0.f, 0.f, 0.f, 0.f);
            if (krow < K) {
                wv = *(const float4*)&W[(size_t)krow * N  + n0 + lc];
                av = *(const float4*)&A[(size_t)krow * Bd + b0 + lc];
            }
            *(float4*)&Ws[lr + rr * 8][lc] = wv;
            *(float4*)&As[lr + rr * 8][lc] = av;
        }
        __syncthreads();
#pragma unroll
        for (int kk = 0; kk < 16; kk++) {
            float a[8], b[8];
            *(float4*)&a[0] = *(const float4*)&Ws[kk][ty * 8];
            *(float4*)&a[4] = *(const float4*)&Ws[kk][ty * 8 + 4];
            *(float4*)&b[0] = *(const float4*)&As[kk][tx * 8];
            *(float4*)&b[4] = *(const float4*)&As[kk][tx * 8 + 4];
#pragma unroll
            for (int i = 0; i < 8; i++)
#pragma unroll
                for (int jj = 0; jj < 8; jj++) acc[i][jj] = fmaf(a[i], b[jj], acc[i][jj]);
        }
        __syncthreads();
    }

#pragma unroll
    for (int i = 0; i < 8; i++) {
        const int n = n0 + ty * 8 + i;
        const float bn = bias_n ? bias_n[n] : 0.f;
        float4 o0, o1;
        o0.x = acc[i][0] + bn; o0.y = acc[i][1] + bn;
        o0.z = acc[i][2] + bn; o0.w = acc[i][3] + bn;
        o1.x = acc[i][4] + bn; o1.y = acc[i][5] + bn;
        o1.z = acc[i][6] + bn; o1.w = acc[i][7] + bn;
        if (bias_b) {
            const int bb = b0 + tx * 8;
            o0.x += bias_b[bb + 0]; o0.y += bias_b[bb + 1];
            o0.z += bias_b[bb + 2]; o0.w += bias_b[bb + 3];
            o1.x += bias_b[bb + 4]; o1.y += bias_b[bb + 5];
            o1.z += bias_b[bb + 6]; o1.w += bias_b[bb + 7];
        }
        *(float4*)&C[(size_t)n * Bd + b0 + tx * 8]     = o0;
        *(float4*)&C[(size_t)n * Bd + b0 + tx * 8 + 4] = o1;
    }
}

// ---------------- per-(t,n) BN stats of XT -> folded affine ----------------
__global__ __launch_bounds__(256) void x_stats(const float* __restrict__ XT,
                                               const float* __restrict__ gih,
                                               const float* __restrict__ bih,
                                               const float* __restrict__ bgate,
                                               const float* __restrict__ bhh,
                                               float* __restrict__ xsA,
                                               float* __restrict__ xsB)
{
    size_t idx = blockIdx.x;
    const float* col = XT + idx * BSZ;
    int tid = threadIdx.x, lane = tid & 31, wid = tid >> 5;
    float s = 0.f, q = 0.f;
    for (int i = tid; i < BSZ; i += 256) { float v = col[i]; s += v; q += v * v; }
    __shared__ float wb[8][3];
#pragma unroll
    for (int o = 16; o > 0; o >>= 1) {
        s += __shfl_down_sync(0xffffffffu, s, o);
        q += __shfl_down_sync(0xffffffffu, q, o);
    }
    if (lane == 0) { wb[wid][0] = s; wb[wid][1] = q; }
    __syncthreads();
    if (tid == 0) {
        float S = 0.f, Q = 0.f;
        for (int w = 0; w < 8; w++) { S += wb[w][0]; Q += wb[w][1]; }
        float m = S * (1.f / BSZ);
        float var = Q * (1.f / BSZ) - m * m;
        float r = rsqrtf(var + EPS_);
        int n = (int)(idx % G4_);
        xsA[idx] = gih[n] * r;
        xsB[idx] = bih[n] - gih[n] * r * m + bgate[n] + bhh[n];
    }
}

// ---------------- persistent fused BN-LSTM layer ----------------
// 128 blocks x 256 threads; block j owns hidden unit j (4 gate columns) over all B.
// Thread handles 4 batch columns. Recurrent h read in fp16 (ping-pong).
__global__ __launch_bounds__(STHR, 1) void bnlstm_layer(
    const float* __restrict__ XT,
    const float* __restrict__ xsA,
    const float* __restrict__ xsB,
    const float* __restrict__ Whh,
    const float* __restrict__ ghh,
    const float* __restrict__ gc,
    const float* __restrict__ bc,
    float* __restrict__ hsOut,
    __half* __restrict__ h16)
{
    const int j = blockIdx.x;
    const int tid = threadIdx.x;
    const int lane = tid & 31, wid = tid >> 5;
    const int b0 = tid * 4;

    __shared__ float WhhS[512];        // WhhS[k*4+q] = Whh[k][j+128q]
    __shared__ float red[8][8];
    __shared__ float stat[8];

#pragma unroll
    for (int i = 0; i < 2; i++) {
        int idx = tid + 256 * i;
        WhhS[idx] = Whh[(size_t)(idx >> 2) * G4_ + j + H_ * (idx & 3)];
    }
    float ghq[4];
#pragma unroll
    for (int q = 0; q < 4; q++) ghq[q] = ghh[j + H_ * q];
    const float gcj = gc[j], bcj = bc[j];
    __syncthreads();

    float cc[4] = {0.f, 0.f, 0.f, 0.f};
    unsigned barTarget = 0;

    for (int t = 0; t < T_; t++) {
        const float* Xt = XT + (size_t)t * G4_ * BSZ;
        float4 xv[4];
        float xa[4], xb[4];
#pragma unroll
        for (int q = 0; q < 4; q++) {
            const int n = j + H_ * q;
            xv[q] = *(const float4*)&Xt[(size_t)n * BSZ + b0];
            xa[q] = xsA[t * G4_ + n];
            xb[q] = xsB[t * G4_ + n];
        }

        float gate[4][4];
        if (t == 0) {
#pragma unroll
            for (int q = 0; q < 4; q++) {
                gate[q][0] = fmaf(xa[q], xv[q].x, xb[q]);
                gate[q][1] = fmaf(xa[q], xv[q].y, xb[q]);
                gate[q][2] = fmaf(xa[q], xv[q].z, xb[q]);
                gate[q][3] = fmaf(xa[q], xv[q].w, xb[q]);
            }
        } else {
            const __half* hp = h16 + (size_t)((t - 1) & 1) * H_ * BSZ + b0;
            float acc[4][4];
#pragma unroll
            for (int q = 0; q < 4; q++)
#pragma unroll
                for (int r = 0; r < 4; r++) acc[q][r] = 0.f;
#pragma unroll 4
            for (int k = 0; k < H_; k++) {
                const uint2 hraw = *(const uint2*)&hp[(size_t)k * BSZ];
                const float2 f01 = __half22float2(*(const __half2*)&hraw.x);
                const float2 f23 = __half22float2(*(const __half2*)&hraw.y);
                const float4 wv = *(const float4*)&WhhS[k * 4];
                acc[0][0] = fmaf(wv.x, f01.x, acc[0][0]); acc[0][1] = fmaf(wv.x, f01.y, acc[0][1]);
                acc[0][2] = fmaf(wv.x, f23.x, acc[0][2]); acc[0][3] = fmaf(wv.x, f23.y, acc[0][3]);
                acc[1][0] = fmaf(wv.y, f01.x, acc[1][0]); acc[1][1] = fmaf(wv.y, f01.y, acc[1][1]);
                acc[1][2] = fmaf(wv.y, f23.x, acc[1][2]); acc[1][3] = fmaf(wv.y, f23.y, acc[1][3]);
                acc[2][0] = fmaf(wv.z, f01.x, acc[2][0]); acc[2][1] = fmaf(wv.z, f01.y, acc[2][1]);
                acc[2][2] = fmaf(wv.z, f23.x, acc[2][2]); acc[2][3] = fmaf(wv.z, f23.y, acc[2][3]);
                acc[3][0] = fmaf(wv.w, f01.x, acc[3][0]); acc[3][1] = fmaf(wv.w, f01.y, acc[3][1]);
                acc[3][2] = fmaf(wv.w, f23.x, acc[3][2]); acc[3][3] = fmaf(wv.w, f23.y, acc[3][3]);
            }

            float vals[8];
#pragma unroll
            for (int q = 0; q < 4; q++) {
                vals[q]     = (acc[q][0] + acc[q][1]) + (acc[q][2] + acc[q][3]);
                vals[4 + q] = (acc[q][0]*acc[q][0] + acc[q][1]*acc[q][1]) +
                              (acc[q][2]*acc[q][2] + acc[q][3]*acc[q][3]);
            }
#pragma unroll
            for (int v = 0; v < 8; v++) {
                float x = vals[v];
#pragma unroll
                for (int o = 16; o > 0; o >>= 1) x += __shfl_down_sync(0xffffffffu, x, o);
                if (lane == 0) red[wid][v] = x;
            }
            __syncthreads();
            if (tid < 8) {
                float s = 0.f;
#pragma unroll
                for (int w = 0; w < 8; w++) s += red[w][tid];
                stat[tid] = s;
            }
            __syncthreads();
#pragma unroll
            for (int q = 0; q < 4; q++) {
                const float m   = stat[q] * (1.f / BSZ);
                const float var = stat[4 + q] * (1.f / BSZ) - m * m;
                const float gr  = ghq[q] * rsqrtf(var + EPS_);
                gate[q][0] = fmaf(xa[q], xv[q].x, xb[q]) + gr * (acc[q][0] - m);
                gate[q][1] = fmaf(xa[q], xv[q].y, xb[q]) + gr * (acc[q][1] - m);
                gate[q][2] = fmaf(xa[q], xv[q].z, xb[q]) + gr * (acc[q][2] - m);
                gate[q][3] = fmaf(xa[q], xv[q].w, xb[q]) + gr * (acc[q][3] - m);
            }
        }

        // cell update (gate order f,i,o,g)
        float cs = 0.f, cq = 0.f;
#pragma unroll
        for (int r = 0; r < 4; r++) {
            cc[r] = sigm(gate[0][r]) * cc[r] + sigm(gate[1][r]) * tanh_fast(gate[3][r]);
            cs += cc[r];
            cq += cc[r] * cc[r];
        }
#pragma unroll
        for (int o = 16; o > 0; o >>= 1) {
            cs += __shfl_down_sync(0xffffffffu, cs, o);
            cq += __shfl_down_sync(0xffffffffu, cq, o);
        }
        __syncthreads();
        if (lane == 0) { red[wid][0] = cs; red[wid][1] = cq; }
        __syncthreads();
        if (tid < 2) {
            float s = 0.f;
#pragma unroll
            for (int w = 0; w < 8; w++) s += red[w][tid];
            stat[tid] = s;
        }
        __syncthreads();

        const float mc = stat[0] * (1.f / BSZ);
        const float rc = rsqrtf(stat[1] * (1.f / BSZ) - mc * mc + EPS_);
        float4 hv;
        hv.x = sigm(gate[2][0]) * tanh_fast(fmaf(gcj * rc, cc[0] - mc, bcj));
        hv.y = sigm(gate[2][1]) * tanh_fast(fmaf(gcj * rc, cc[1] - mc, bcj));
        hv.z = sigm(gate[2][2]) * tanh_fast(fmaf(gcj * rc, cc[2] - mc, bcj));
        hv.w = sigm(gate[2][3]) * tanh_fast(fmaf(gcj * rc, cc[3] - mc, bcj));
        *(float4*)&hsOut[(size_t)t * H_ * BSZ + (size_t)j * BSZ + b0] = hv;
        __half2 hh0 = __floats2half2_rn(hv.x, hv.y);
        __half2 hh1 = __floats2half2_rn(hv.z, hv.w);
        uint2 hpack = make_uint2(*(unsigned*)&hh0, *(unsigned*)&hh1);
        *(uint2*)&h16[(size_t)(t & 1) * H_ * BSZ + (size_t)j * BSZ + b0] = hpack;

        if (t < T_ - 1) {
            barTarget += NBLK;
            if (tid == 0) {
                __threadfence();
                atomicAdd(&g_barArr, 1u);
                while (*((volatile unsigned*)&g_barArr) < barTarget) __nanosleep(64);
                __threadfence();
            }
            __syncthreads();
        }
    }
}

// ---------------- launch ----------------
extern "C" void kernel_launch(void* const* d_in, const int* in_sizes, int n_in,
                              void* d_out, int out_size)
{
    const float* seq  = (const float*)d_in[0];
    const float* Wih0 = (const float*)d_in[1];
    const float* Whh0 = (const float*)d_in[2];
    const float* b0   = (const float*)d_in[3];
    const float* gih0 = (const float*)d_in[4];
    const float* bih0 = (const float*)d_in[5];
    const float* ghh0 = (const float*)d_in[6];
    const float* bhh0 = (const float*)d_in[7];
    const float* gc0  = (const float*)d_in[8];
    const float* bc0  = (const float*)d_in[9];
    const float* Wih1 = (const float*)d_in[10];
    const float* Whh1 = (const float*)d_in[11];
    const float* b1   = (const float*)d_in[12];
    const float* gih1 = (const float*)d_in[13];
    const float* bih1 = (const float*)d_in[14];
    const float* ghh1 = (const float*)d_in[15];
    const float* bhh1 = (const float*)d_in[16];
    const float* gc1  = (const float*)d_in[17];
    const float* bc1  = (const float*)d_in[18];
    const float* fcw  = (const float*)d_in[19];
    const float* fcb  = (const float*)d_in[20];
    const float* decw = (const float*)d_in[21];
    const float* decb = (const float*)d_in[22];
    float* out = (float*)d_out;
    (void)in_sizes; (void)n_in; (void)out_size;

    float *xTm, *XT, *hs0T, *hs1T, *xsA, *xsB, *embT;
    __half* h16;
    cudaGetSymbolAddress((void**)&xTm,  g_xTm);
    cudaGetSymbolAddress((void**)&XT,   g_XT);
    cudaGetSymbolAddress((void**)&hs0T, g_hs0T);
    cudaGetSymbolAddress((void**)&hs1T, g_hs1T);
    cudaGetSymbolAddress((void**)&xsA,  g_xsA);
    cudaGetSymbolAddress((void**)&xsB,  g_xsB);
    cudaGetSymbolAddress((void**)&embT, g_embT);
    cudaGetSymbolAddress((void**)&h16,  g_h16);

    transpose_seq<<<dim3(BSZ / 128, T_), 256>>>(seq, xTm);

    // layer-0 input GEMM + folded BN stats
    tn_gemm128<<<dim3(BSZ / 128, G4_ / 128, T_), 256>>>(Wih0, xTm, XT, IN_, G4_, BSZ,
                                                        (long long)IN_ * BSZ, (long long)G4_ * BSZ,
                                                        nullptr, nullptr);
    x_stats<<<T_ * G4_, 256>>>(XT, gih0, bih0, b0, bhh0, xsA, xsB);

    reset_bar_k<<<1, 1>>>();
    bnlstm_layer<<<NBLK, STHR>>>(XT, xsA, xsB, Whh0, ghh0, gc0, bc0, hs0T, h16);

    // layer-1 input GEMM + folded BN stats
    tn_gemm128<<<dim3(BSZ / 128, G4_ / 128, T_), 256>>>(Wih1, hs0T, XT, H_, G4_, BSZ,
                                                        (long long)H_ * BSZ, (long long)G4_ * BSZ,
                                                        nullptr, nullptr);
    x_stats<<<T_ * G4_, 256>>>(XT, gih1, bih1, b1, bhh1, xsA, xsB);

    reset_bar_k<<<1, 1>>>();
    bnlstm_layer<<<NBLK, STHR>>>(XT, xsA, xsB, Whh1, ghh1, gc1, bc1, hs1T, h16);

    // fc on last hidden of layer 1
    tn_gemm128<<<dim3(BSZ / 128, OUT_ / 128, 1), 256>>>(fcw, hs1T + (size_t)(T_ - 1) * H_ * BSZ,
                                                        embT, H_, OUT_, BSZ,
                                                        0, 0, fcb, nullptr);

    // decoder
    tn_gemm128<<<dim3(MDEC / 128, BSZ / 128, 1), 256>>>(embT, decw, out, OUT_, BSZ, MDEC,
                                                        0, 0, nullptr, decb);
}

// round 5
// speedup vs baseline: 1.3423x; 1.3423x over previous
#include <cuda_runtime.h>
#include <cuda_fp16.h>
#include <math.h>

#define T_    128
#define BSZ   1024
#define IN_   75
#define H_    128
#define G4_   512
#define OUT_  256
#define MDEC  (128*75)
#define EPS_  1e-5f
#define NBLK  128
#define NTHR  512

typedef unsigned long long ull;

// ---------------- device scratch ----------------
__device__ float  g_xTm [(size_t)T_*IN_*BSZ];
__device__ float  g_XT  [(size_t)T_*G4_*BSZ];
__device__ float  g_hs0T[(size_t)T_*H_*BSZ];
__device__ float  g_hs1T[(size_t)T_*H_*BSZ];
__device__ __half g_h16 [(size_t)2*H_*BSZ];    // ping-pong fp16 recurrent h
__device__ float  g_xsA [(size_t)T_*G4_];
__device__ float  g_xsB [(size_t)T_*G4_];
__device__ float  g_embT[(size_t)OUT_*BSZ];
__device__ unsigned g_barArr;

__global__ void reset_bar_k() { g_barArr = 0u; }

__device__ __forceinline__ float tanh_fast(float x) {
    float y; asm("tanh.approx.f32 %0, %1;" : "=f"(y) : "f"(x)); return y;
}
__device__ __forceinline__ float sigm(float x) {
    return fmaf(0.5f, tanh_fast(0.5f * x), 0.5f);
}
__device__ __forceinline__ ull pack2(float lo, float hi) {
    ull r; asm("mov.b64 %0, {%1, %2};" : "=l"(r) : "f"(lo), "f"(hi)); return r;
}
__device__ __forceinline__ void unpack2(ull v, float& lo, float& hi) {
    asm("mov.b64 {%0, %1}, %2;" : "=f"(lo), "=f"(hi) : "l"(v));
}
__device__ __forceinline__ void fma2(ull& d, ull a, ull b) {
    asm("fma.rn.f32x2 %0, %1, %2, %0;" : "+l"(d) : "l"(a), "l"(b));
}

// ---------------- transpose sequences (B,T,IN) -> (T,IN,B) ----------------
__global__ __launch_bounds__(256) void transpose_seq(const float* __restrict__ seq,
                                                     float* __restrict__ xTm)
{
    int t  = blockIdx.y;
    int b0 = blockIdx.x * 128;
    __shared__ float sm[128 * 77];
    int tid = threadIdx.x;
    for (int i = tid; i < 128 * IN_; i += 256) {
        int bl = i / IN_, k = i % IN_;
        sm[bl * 77 + k] = seq[(size_t)(b0 + bl) * (T_ * IN_) + (size_t)t * IN_ + k];
    }
    __syncthreads();
    for (int i = tid; i < IN_ * 128; i += 256) {
        int k = i / 128, bl = i % 128;
        xTm[(size_t)t * IN_ * BSZ + (size_t)k * BSZ + b0 + bl] = sm[bl * 77 + k];
    }
}

// ---------------- TN SGEMM 128x128 tile, BK=16, 8x8 micro-tile, FFMA2 ----------------
// C[n][b] = sum_k W[k][n] * A[k][b].  N,Bd multiples of 128 (K arbitrary).
__global__ __launch_bounds__(256) void tn_gemm128(const float* __restrict__ W,
                                                  const float* __restrict__ A,
                                                  float* __restrict__ C,
                                                  int K, int N, int Bd,
                                                  long long strideA, long long strideC,
                                                  const float* __restrict__ bias_n,
                                                  const float* __restrict__ bias_b)
{
    A += (size_t)blockIdx.z * strideA;
    C += (size_t)blockIdx.z * strideC;
    const int n0 = blockIdx.y * 128;
    const int b0 = blockIdx.x * 128;

    __shared__ float Ws[16][128];
    __shared__ float As[16][128];

    const int tid = threadIdx.x;
    const int lr = tid / 32;
    const int lc = (tid % 32) * 4;
    const int tx = tid % 16;          // batch dir
    const int ty = tid / 16;          // n dir

    ull accP[8][4];                   // [n-row][batch-pair], packed fp32x2
#pragma unroll
    for (int i = 0; i < 8; i++)
#pragma unroll
        for (int jp = 0; jp < 4; jp++) accP[i][jp] = 0ull;

    for (int k0 = 0; k0 < K; k0 += 16) {
#pragma unroll
        for (int rr = 0; rr < 2; rr++) {
            const int krow = k0 + lr + rr * 8;
            float4 wv = make_float4(0.f, 0.f, 0.f, 0.f);
            float4 av = make_float4(0.f, 0.f, 0.f, 0.f);
            if (krow < K) {
                wv = *(const float4*)&W[(size_t)krow * N  + n0 + lc];
                av = *(const float4*)&A[(size_t)krow * Bd + b0 + lc];
            }
            *(float4*)&Ws[lr + rr * 8][lc] = wv;
            *(float4*)&As[lr + rr * 8][lc] = av;
        }
        __syncthreads();
#pragma unroll
        for (int kk = 0; kk < 16; kk++) {
            float a[8];
            float4 bq0 = *(const float4*)&As[kk][tx * 8];
            float4 bq1 = *(const float4*)&As[kk][tx * 8 + 4];
            *(float4*)&a[0] = *(const float4*)&Ws[kk][ty * 8];
            *(float4*)&a[4] = *(const float4*)&Ws[kk][ty * 8 + 4];
            ull bp[4];
            bp[0] = pack2(bq0.x, bq0.y);
            bp[1] = pack2(bq0.z, bq0.w);
            bp[2] = pack2(bq1.x, bq1.y);
            bp[3] = pack2(bq1.z, bq1.w);
#pragma unroll
            for (int i = 0; i < 8; i++) {
                const ull ad = pack2(a[i], a[i]);
#pragma unroll
                for (int jp = 0; jp < 4; jp++) fma2(accP[i][jp], ad, bp[jp]);
            }
        }
        __syncthreads();
    }

#pragma unroll
    for (int i = 0; i < 8; i++) {
        const int n = n0 + ty * 8 + i;
        const float bn = bias_n ? bias_n[n] : 0.f;
        float v[8];
#pragma unroll
        for (int jp = 0; jp < 4; jp++) unpack2(accP[i][jp], v[2 * jp], v[2 * jp + 1]);
        float4 o0, o1;
        o0.x = v[0] + bn; o0.y = v[1] + bn; o0.z = v[2] + bn; o0.w = v[3] + bn;
        o1.x = v[4] + bn; o1.y = v[5] + bn; o1.z = v[6] + bn; o1.w = v[7] + bn;
        if (bias_b) {
            const int bb = b0 + tx * 8;
            o0.x += bias_b[bb + 0]; o0.y += bias_b[bb + 1];
            o0.z += bias_b[bb + 2]; o0.w += bias_b[bb + 3];
            o1.x += bias_b[bb + 4]; o1.y += bias_b[bb + 5];
            o1.z += bias_b[bb + 6]; o1.w += bias_b[bb + 7];
        }
        *(float4*)&C[(size_t)n * Bd + b0 + tx * 8]     = o0;
        *(float4*)&C[(size_t)n * Bd + b0 + tx * 8 + 4] = o1;
    }
}

// ---------------- per-(t,n) BN stats of XT -> folded affine ----------------
__global__ __launch_bounds__(256) void x_stats(const float* __restrict__ XT,
                                               const float* __restrict__ gih,
                                               const float* __restrict__ bih,
                                               const float* __restrict__ bgate,
                                               const float* __restrict__ bhh,
                                               float* __restrict__ xsA,
                                               float* __restrict__ xsB)
{
    size_t idx = blockIdx.x;
    const float* col = XT + idx * BSZ;
    int tid = threadIdx.x, lane = tid & 31, wid = tid >> 5;
    float s = 0.f, q = 0.f;
    for (int i = tid; i < BSZ; i += 256) { float v = col[i]; s += v; q += v * v; }
    __shared__ float wb[8][3];
#pragma unroll
    for (int o = 16; o > 0; o >>= 1) {
        s += __shfl_down_sync(0xffffffffu, s, o);
        q += __shfl_down_sync(0xffffffffu, q, o);
    }
    if (lane == 0) { wb[wid][0] = s; wb[wid][1] = q; }
    __syncthreads();
    if (tid == 0) {
        float S = 0.f, Q = 0.f;
        for (int w = 0; w < 8; w++) { S += wb[w][0]; Q += wb[w][1]; }
        float m = S * (1.f / BSZ);
        float var = Q * (1.f / BSZ) - m * m;
        float r = rsqrtf(var + EPS_);
        int n = (int)(idx % G4_);
        xsA[idx] = gih[n] * r;
        xsB[idx] = bih[n] - gih[n] * r * m + bgate[n] + bhh[n];
    }
}

// ---------------- persistent fused BN-LSTM layer ----------------
// 128 blocks x 512 threads; block j owns hidden unit j (4 gate columns) over all B.
// Thread handles 2 batch columns. Recurrent h read as fp16 ping-pong; GEMM in FFMA2.
__global__ __launch_bounds__(NTHR, 1) void bnlstm_layer(
    const float* __restrict__ XT,
    const float* __restrict__ xsA,
    const float* __restrict__ xsB,
    const float* __restrict__ Whh,
    const float* __restrict__ ghh,
    const float* __restrict__ gc,
    const float* __restrict__ bc,
    float* __restrict__ hsOut,
    __half* __restrict__ h16)
{
    const int j = blockIdx.x;
    const int tid = threadIdx.x;
    const int lane = tid & 31, wid = tid >> 5;
    const int b0 = tid * 2;

    __shared__ float4 WhhS4[128];      // WhhS4[k] = (W[k][j], W[k][j+128], W[k][j+256], W[k][j+384])
    __shared__ float red[16][8];
    __shared__ float stat[8];

    {
        float* WhhS = (float*)WhhS4;
        WhhS[tid] = Whh[(size_t)(tid >> 2) * G4_ + j + H_ * (tid & 3)];
    }
    float ghq[4];
#pragma unroll
    for (int q = 0; q < 4; q++) ghq[q] = ghh[j + H_ * q];
    const float gcj = gc[j], bcj = bc[j];
    __syncthreads();

    float cc0 = 0.f, cc1 = 0.f;
    unsigned barTarget = 0;

    for (int t = 0; t < T_; t++) {
        const float* Xt = XT + (size_t)t * G4_ * BSZ;
        float2 xv[4];
        float xa[4], xb[4];
#pragma unroll
        for (int q = 0; q < 4; q++) {
            const int n = j + H_ * q;
            xv[q] = *(const float2*)&Xt[(size_t)n * BSZ + b0];
            xa[q] = xsA[t * G4_ + n];
            xb[q] = xsB[t * G4_ + n];
        }

        float gate[4][2];
        if (t == 0) {
#pragma unroll
            for (int q = 0; q < 4; q++) {
                gate[q][0] = fmaf(xa[q], xv[q].x, xb[q]);
                gate[q][1] = fmaf(xa[q], xv[q].y, xb[q]);
            }
        } else {
            // GEMM: acc[q][r] = sum_k W[k][j+128q] * h(t-1)[k][b0+r]   (packed over q-pairs)
            const __half* hp = h16 + (size_t)((t - 1) & 1) * H_ * BSZ + b0;
            ull aP01_0 = 0ull, aP23_0 = 0ull;   // gates{0,1},{2,3} for col 0
            ull aP01_1 = 0ull, aP23_1 = 0ull;   // for col 1
#pragma unroll 8
            for (int k = 0; k < H_; k++) {
                const __half2 hraw = *(const __half2*)&hp[(size_t)k * BSZ];
                const float2 hf = __half22float2(hraw);
                const float4 wv = WhhS4[k];
                const ull w01 = pack2(wv.x, wv.y);
                const ull w23 = pack2(wv.z, wv.w);
                const ull h0d = pack2(hf.x, hf.x);
                const ull h1d = pack2(hf.y, hf.y);
                fma2(aP01_0, w01, h0d);
                fma2(aP23_0, w23, h0d);
                fma2(aP01_1, w01, h1d);
                fma2(aP23_1, w23, h1d);
            }
            float acc[4][2];
            unpack2(aP01_0, acc[0][0], acc[1][0]);
            unpack2(aP23_0, acc[2][0], acc[3][0]);
            unpack2(aP01_1, acc[0][1], acc[1][1]);
            unpack2(aP23_1, acc[2][1], acc[3][1]);

            // block-local BN stats over B for the 4 gate columns
            float vals[8];
#pragma unroll
            for (int q = 0; q < 4; q++) {
                vals[q]     = acc[q][0] + acc[q][1];
                vals[4 + q] = acc[q][0]*acc[q][0] + acc[q][1]*acc[q][1];
            }
#pragma unroll
            for (int v = 0; v < 8; v++) {
                float x = vals[v];
#pragma unroll
                for (int o = 16; o > 0; o >>= 1) x += __shfl_down_sync(0xffffffffu, x, o);
                if (lane == 0) red[wid][v] = x;
            }
            __syncthreads();
            if (tid < 8) {
                float s = 0.f;
#pragma unroll
                for (int w = 0; w < 16; w++) s += red[w][tid];
                stat[tid] = s;
            }
            __syncthreads();
#pragma unroll
            for (int q = 0; q < 4; q++) {
                const float m   = stat[q] * (1.f / BSZ);
                const float var = stat[4 + q] * (1.f / BSZ) - m * m;
                const float gr  = ghq[q] * rsqrtf(var + EPS_);
                gate[q][0] = fmaf(xa[q], xv[q].x, xb[q]) + gr * (acc[q][0] - m);
                gate[q][1] = fmaf(xa[q], xv[q].y, xb[q]) + gr * (acc[q][1] - m);
            }
        }

        // cell update (gate order f,i,o,g)
        cc0 = sigm(gate[0][0]) * cc0 + sigm(gate[1][0]) * tanh_fast(gate[3][0]);
        cc1 = sigm(gate[0][1]) * cc1 + sigm(gate[1][1]) * tanh_fast(gate[3][1]);
        float cs = cc0 + cc1;
        float cq = cc0 * cc0 + cc1 * cc1;
#pragma unroll
        for (int o = 16; o > 0; o >>= 1) {
            cs += __shfl_down_sync(0xffffffffu, cs, o);
            cq += __shfl_down_sync(0xffffffffu, cq, o);
        }
        __syncthreads();
        if (lane == 0) { red[wid][0] = cs; red[wid][1] = cq; }
        __syncthreads();
        if (tid < 2) {
            float s = 0.f;
#pragma unroll
            for (int w = 0; w < 16; w++) s += red[w][tid];
            stat[tid] = s;
        }
        __syncthreads();

        const float mc = stat[0] * (1.f / BSZ);
        const float rc = rsqrtf(stat[1] * (1.f / BSZ) - mc * mc + EPS_);
        float2 hv;
        hv.x = sigm(gate[2][0]) * tanh_fast(fmaf(gcj * rc, cc0 - mc, bcj));
        hv.y = sigm(gate[2][1]) * tanh_fast(fmaf(gcj * rc, cc1 - mc, bcj));
        *(float2*)&hsOut[(size_t)t * H_ * BSZ + (size_t)j * BSZ + b0] = hv;
        __half2 hh = __floats2half2_rn(hv.x, hv.y);
        *(__half2*)&h16[(size_t)(t & 1) * H_ * BSZ + (size_t)j * BSZ + b0] = hh;

        if (t < T_ - 1) {
            barTarget += NBLK;
            if (tid == 0) {
                __threadfence();
                atomicAdd(&g_barArr, 1u);
                while (*((volatile unsigned*)&g_barArr) < barTarget) __nanosleep(64);
                __threadfence();
            }
            __syncthreads();
        }
    }
}

// ---------------- launch ----------------
extern "C" void kernel_launch(void* const* d_in, const int* in_sizes, int n_in,
                              void* d_out, int out_size)
{
    const float* seq  = (const float*)d_in[0];
    const float* Wih0 = (const float*)d_in[1];
    const float* Whh0 = (const float*)d_in[2];
    const float* b0   = (const float*)d_in[3];
    const float* gih0 = (const float*)d_in[4];
    const float* bih0 = (const float*)d_in[5];
    const float* ghh0 = (const float*)d_in[6];
    const float* bhh0 = (const float*)d_in[7];
    const float* gc0  = (const float*)d_in[8];
    const float* bc0  = (const float*)d_in[9];
    const float* Wih1 = (const float*)d_in[10];
    const float* Whh1 = (const float*)d_in[11];
    const float* b1   = (const float*)d_in[12];
    const float* gih1 = (const float*)d_in[13];
    const float* bih1 = (const float*)d_in[14];
    const float* ghh1 = (const float*)d_in[15];
    const float* bhh1 = (const float*)d_in[16];
    const float* gc1  = (const float*)d_in[17];
    const float* bc1  = (const float*)d_in[18];
    const float* fcw  = (const float*)d_in[19];
    const float* fcb  = (const float*)d_in[20];
    const float* decw = (const float*)d_in[21];
    const float* decb = (const float*)d_in[22];
    float* out = (float*)d_out;
    (void)in_sizes; (void)n_in; (void)out_size;

    float *xTm, *XT, *hs0T, *hs1T, *xsA, *xsB, *embT;
    __half* h16;
    cudaGetSymbolAddress((void**)&xTm,  g_xTm);
    cudaGetSymbolAddress((void**)&XT,   g_XT);
    cudaGetSymbolAddress((void**)&hs0T, g_hs0T);
    cudaGetSymbolAddress((void**)&hs1T, g_hs1T);
    cudaGetSymbolAddress((void**)&xsA,  g_xsA);
    cudaGetSymbolAddress((void**)&xsB,  g_xsB);
    cudaGetSymbolAddress((void**)&embT, g_embT);
    cudaGetSymbolAddress((void**)&h16,  g_h16);

    transpose_seq<<<dim3(BSZ / 128, T_), 256>>>(seq, xTm);

    // layer-0 input GEMM + folded BN stats
    tn_gemm128<<<dim3(BSZ / 128, G4_ / 128, T_), 256>>>(Wih0, xTm, XT, IN_, G4_, BSZ,
                                                        (long long)IN_ * BSZ, (long long)G4_ * BSZ,
                                                        nullptr, nullptr);
    x_stats<<<T_ * G4_, 256>>>(XT, gih0, bih0, b0, bhh0, xsA, xsB);

    reset_bar_k<<<1, 1>>>();
    bnlstm_layer<<<NBLK, NTHR>>>(XT, xsA, xsB, Whh0, ghh0, gc0, bc0, hs0T, h16);

    // layer-1 input GEMM + folded BN stats
    tn_gemm128<<<dim3(BSZ / 128, G4_ / 128, T_), 256>>>(Wih1, hs0T, XT, H_, G4_, BSZ,
                                                        (long long)H_ * BSZ, (long long)G4_ * BSZ,
                                                        nullptr, nullptr);
    x_stats<<<T_ * G4_, 256>>>(XT, gih1, bih1, b1, bhh1, xsA, xsB);

    reset_bar_k<<<1, 1>>>();
    bnlstm_layer<<<NBLK, NTHR>>>(XT, xsA, xsB, Whh1, ghh1, gc1, bc1, hs1T, h16);

    // fc on last hidden of layer 1
    tn_gemm128<<<dim3(BSZ / 128, OUT_ / 128, 1), 256>>>(fcw, hs1T + (size_t)(T_ - 1) * H_ * BSZ,
                                                        embT, H_, OUT_, BSZ,
                                                        0, 0, fcb, nullptr);

    // decoder
    tn_gemm128<<<dim3(MDEC / 128, BSZ / 128, 1), 256>>>(embT, decw, out, OUT_, BSZ, MDEC,
                                                        0, 0, nullptr, decb);
}

// round 7
// speedup vs baseline: 1.5214x; 1.1334x over previous
#include <cuda_runtime.h>
#include <cuda_fp16.h>
#include <math.h>
#include <stdint.h>

#define T_    128
#define BSZ   1024
#define IN_   75
#define H_    128
#define G4_   512
#define OUT_  256
#define MDEC  (128*75)
#define EPS_  1e-5f
#define NBLK  128
#define NTHR  512

typedef unsigned long long ull;

// ---------------- device scratch ----------------
__device__ __half g_XT  [(size_t)T_*G4_*BSZ];  // (T, 4H, B) fp16 gate pre-activations
__device__ __half g_xbk [(size_t)T_*BSZ*128];  // (T, B, 128) fp16 padded input, k-contig
__device__ __half g_hbk [(size_t)T_*BSZ*128];  // (T, B, 128) fp16 hs0 transposed, k-contig
__device__ __half g_Wt  [(size_t)G4_*128];     // (512, 128) fp16 W^T k-contig
__device__ float  g_hs0T[(size_t)T_*H_*BSZ];
__device__ float  g_hs1T[(size_t)T_*H_*BSZ];
__device__ __half g_h16 [(size_t)2*H_*BSZ];    // ping-pong fp16 recurrent h
__device__ float  g_xsA [(size_t)T_*G4_];
__device__ float  g_xsB [(size_t)T_*G4_];
__device__ float  g_embT[(size_t)OUT_*BSZ];
__device__ unsigned g_barArr;

__global__ void reset_bar_k() { g_barArr = 0u; }

__device__ __forceinline__ float tanh_fast(float x) {
    float y; asm("tanh.approx.f32 %0, %1;" : "=f"(y) : "f"(x)); return y;
}
__device__ __forceinline__ float sigm(float x) {
    return fmaf(0.5f, tanh_fast(0.5f * x), 0.5f);
}
__device__ __forceinline__ ull pack2(float lo, float hi) {
    ull r; asm("mov.b64 %0, {%1, %2};" : "=l"(r) : "f"(lo), "f"(hi)); return r;
}
__device__ __forceinline__ void unpack2(ull v, float& lo, float& hi) {
    asm("mov.b64 {%0, %1}, %2;" : "=f"(lo), "=f"(hi) : "l"(v));
}
__device__ __forceinline__ void fma2(ull& d, ull a, ull b) {
    asm("fma.rn.f32x2 %0, %1, %2, %0;" : "+l"(d) : "l"(a), "l"(b));
}
__device__ __forceinline__ void mma16816(float* c, const uint32_t* a, const uint32_t* b) {
    asm volatile(
        "mma.sync.aligned.m16n8k16.row.col.f32.f16.f16.f32 "
        "{%0,%1,%2,%3}, {%4,%5,%6,%7}, {%8,%9}, {%0,%1,%2,%3};"
        : "+f"(c[0]), "+f"(c[1]), "+f"(c[2]), "+f"(c[3])
        : "r"(a[0]), "r"(a[1]), "r"(a[2]), "r"(a[3]), "r"(b[0]), "r"(b[1]));
}

// ================= HMMA fp16 FF GEMM =================
// XT[t][n][b] = sum_k Wt[n][k] * Xbk[t][b][k]
// Block tile: 128 gates x 128 batch, K=128. 8 warps = 4(m) x 2(n); warp 32x64.
#define SROW 136   // padded row stride in halfs (word-stride 68 -> conflict-free frags)

__global__ __launch_bounds__(256) void hmma_gemm(
    const __half* __restrict__ Wt,    // (512, 128)
    const __half* __restrict__ Xbk,   // (T, B, 128)
    __half* __restrict__ XT)          // (T, 512, B)
{
    extern __shared__ __half sm[];
    __half* As = sm;                  // 128 x SROW
    __half* Bs = sm + 128 * SROW;     // 128 x SROW

    const int t  = blockIdx.z;
    const int n0 = blockIdx.y * 128;
    const int b0 = blockIdx.x * 128;
    const int tid = threadIdx.x;
    const int wid = tid >> 5, lane = tid & 31;
    const int wm = wid >> 1;          // 0..3  -> m offset wm*32
    const int wn = wid & 1;           // 0..1  -> n offset wn*64

    // stage A (gates x k) and B (batch x k) tiles, float4 = 8 halfs
    {
        const float4* Ag = (const float4*)(Wt + (size_t)n0 * 128);
        const float4* Bg = (const float4*)(Xbk + ((size_t)t * BSZ + b0) * 128);
#pragma unroll
        for (int it = 0; it < 8; it++) {
            int i = tid + 256 * it;        // 0..2047
            int r = i >> 4, c8 = (i & 15) * 8;
            *(float4*)&As[r * SROW + c8] = Ag[i];
            *(float4*)&Bs[r * SROW + c8] = Bg[i];
        }
    }
    __syncthreads();

    float acc[2][8][4];
#pragma unroll
    for (int mt = 0; mt < 2; mt++)
#pragma unroll
        for (int nt = 0; nt < 8; nt++)
#pragma unroll
            for (int e = 0; e < 4; e++) acc[mt][nt][e] = 0.f;

    const int fr = lane >> 2;          // fragment row 0..7
    const int kp = (lane & 3) * 2;     // fragment k-pair

#pragma unroll
    for (int ks = 0; ks < 8; ks++) {
        const int k0 = ks * 16;
        uint32_t a[2][4];
#pragma unroll
        for (int mt = 0; mt < 2; mt++) {
            const int mr = wm * 32 + mt * 16;
            a[mt][0] = *(const uint32_t*)&As[(mr + fr)     * SROW + k0 + kp];
            a[mt][1] = *(const uint32_t*)&As[(mr + fr + 8) * SROW + k0 + kp];
            a[mt][2] = *(const uint32_t*)&As[(mr + fr)     * SROW + k0 + kp + 8];
            a[mt][3] = *(const uint32_t*)&As[(mr + fr + 8) * SROW + k0 + kp + 8];
        }
#pragma unroll
        for (int nt = 0; nt < 8; nt++) {
            const int bc = wn * 64 + nt * 8 + fr;
            uint32_t b[2];
            b[0] = *(const uint32_t*)&Bs[bc * SROW + k0 + kp];
            b[1] = *(const uint32_t*)&Bs[bc * SROW + k0 + kp + 8];
            mma16816(acc[0][nt], a[0], b);
            mma16816(acc[1][nt], a[1], b);
        }
    }

    // write fp16 XT: c0,c1 = (row fr, cols 2(lane&3)+{0,1}); c2,c3 = row fr+8
#pragma unroll
    for (int mt = 0; mt < 2; mt++) {
        const int n = n0 + wm * 32 + mt * 16 + fr;
        __half* R0 = XT + ((size_t)t * G4_ + n)     * BSZ + b0;
        __half* R1 = XT + ((size_t)t * G4_ + n + 8) * BSZ + b0;
#pragma unroll
        for (int nt = 0; nt < 8; nt++) {
            const int bcol = wn * 64 + nt * 8 + (lane & 3) * 2;
            *(__half2*)&R0[bcol] = __floats2half2_rn(acc[mt][nt][0], acc[mt][nt][1]);
            *(__half2*)&R1[bcol] = __floats2half2_rn(acc[mt][nt][2], acc[mt][nt][3]);
        }
    }
}

// ---------------- operand prep kernels ----------------
__global__ __launch_bounds__(256) void w_to_t(const float* __restrict__ W,
                                              __half* __restrict__ Wt, int K)
{
    int i = blockIdx.x * 256 + threadIdx.x;   // over 512*128
    int n = i >> 7, k = i & 127;
    Wt[i] = __float2half(k < K ? W[(size_t)k * G4_ + n] : 0.f);
}

__global__ __launch_bounds__(256) void x_to_bk(const float* __restrict__ seq,
                                               __half* __restrict__ xbk)
{
    int t = blockIdx.y;
    size_t i = (size_t)blockIdx.x * 256 + threadIdx.x;   // over B*128
    int b = (int)(i >> 7), k = (int)(i & 127);
    float v = (k < IN_) ? seq[((size_t)b * T_ + t) * IN_ + k] : 0.f;
    xbk[(size_t)t * BSZ * 128 + i] = __float2half(v);
}

__global__ __launch_bounds__(256) void h_to_bk(const float* __restrict__ hsT,
                                               __half* __restrict__ hbk)
{
    int t = blockIdx.z;
    int h0 = blockIdx.y * 32;
    int b0 = blockIdx.x * 32;
    __shared__ float sm[32][33];
    int tid = threadIdx.x;
    int lx = tid & 31, ly = tid >> 5;
#pragma unroll
    for (int i = 0; i < 4; i++) {
        int h = h0 + ly + i * 8;
        sm[ly + i * 8][lx] = hsT[((size_t)t * H_ + h) * BSZ + b0 + lx];
    }
    __syncthreads();
#pragma unroll
    for (int i = 0; i < 4; i++) {
        int b = b0 + ly + i * 8;
        hbk[((size_t)t * BSZ + b) * 128 + h0 + lx] = __float2half(sm[lx][ly + i * 8]);
    }
}

// ---------------- TN SGEMM 128x128 FFMA2 (fc + decoder, fp32) ----------------
__global__ __launch_bounds__(256) void tn_gemm128(const float* __restrict__ W,
                                                  const float* __restrict__ A,
                                                  float* __restrict__ C,
                                                  int K, int N, int Bd,
                                                  long long strideA, long long strideC,
                                                  const float* __restrict__ bias_n,
                                                  const float* __restrict__ bias_b)
{
    A += (size_t)blockIdx.z * strideA;
    C += (size_t)blockIdx.z * strideC;
    const int n0 = blockIdx.y * 128;
    const int b0 = blockIdx.x * 128;

    __shared__ float Ws[16][128];
    __shared__ float As[16][128];

    const int tid = threadIdx.x;
    const int lr = tid / 32;
    const int lc = (tid % 32) * 4;
    const int tx = tid % 16;
    const int ty = tid / 16;

    ull accP[8][4];
#pragma unroll
    for (int i = 0; i < 8; i++)
#pragma unroll
        for (int jp = 0; jp < 4; jp++) accP[i][jp] = 0ull;

    for (int k0 = 0; k0 < K; k0 += 16) {
#pragma unroll
        for (int rr = 0; rr < 2; rr++) {
            const int krow = k0 + lr + rr * 8;
            float4 wv = make_float4(0.f, 0.f, 0.f, 0.f);
            float4 av = make_float4(0.f, 0.f, 0.f, 0.f);
            if (krow < K) {
                wv = *(const float4*)&W[(size_t)krow * N  + n0 + lc];
                av = *(const float4*)&A[(size_t)krow * Bd + b0 + lc];
            }
            *(float4*)&Ws[lr + rr * 8][lc] = wv;
            *(float4*)&As[lr + rr * 8][lc] = av;
        }
        __syncthreads();
#pragma unroll
        for (int kk = 0; kk < 16; kk++) {
            float a[8];
            float4 bq0 = *(const float4*)&As[kk][tx * 8];
            float4 bq1 = *(const float4*)&As[kk][tx * 8 + 4];
            *(float4*)&a[0] = *(const float4*)&Ws[kk][ty * 8];
            *(float4*)&a[4] = *(const float4*)&Ws[kk][ty * 8 + 4];
            ull bp[4];
            bp[0] = pack2(bq0.x, bq0.y);
            bp[1] = pack2(bq0.z, bq0.w);
            bp[2] = pack2(bq1.x, bq1.y);
            bp[3] = pack2(bq1.z, bq1.w);
#pragma unroll
            for (int i = 0; i < 8; i++) {
                const ull ad = pack2(a[i], a[i]);
#pragma unroll
                for (int jp = 0; jp < 4; jp++) fma2(accP[i][jp], ad, bp[jp]);
            }
        }
        __syncthreads();
    }

#pragma unroll
    for (int i = 0; i < 8; i++) {
        const int n = n0 + ty * 8 + i;
        const float bn = bias_n ? bias_n[n] : 0.f;
        float v[8];
#pragma unroll
        for (int jp = 0; jp < 4; jp++) unpack2(accP[i][jp], v[2 * jp], v[2 * jp + 1]);
        float4 o0, o1;
        o0.x = v[0] + bn; o0.y = v[1] + bn; o0.z = v[2] + bn; o0.w = v[3] + bn;
        o1.x = v[4] + bn; o1.y = v[5] + bn; o1.z = v[6] + bn; o1.w = v[7] + bn;
        if (bias_b) {
            const int bb = b0 + tx * 8;
            o0.x += bias_b[bb + 0]; o0.y += bias_b[bb + 1];
            o0.z += bias_b[bb + 2]; o0.w += bias_b[bb + 3];
            o1.x += bias_b[bb + 4]; o1.y += bias_b[bb + 5];
            o1.z += bias_b[bb + 6]; o1.w += bias_b[bb + 7];
        }
        *(float4*)&C[(size_t)n * Bd + b0 + tx * 8]     = o0;
        *(float4*)&C[(size_t)n * Bd + b0 + tx * 8 + 4] = o1;
    }
}

// ---------------- per-(t,n) BN stats of fp16 XT -> folded affine ----------------
__global__ __launch_bounds__(256) void x_stats(const __half* __restrict__ XT,
                                               const float* __restrict__ gih,
                                               const float* __restrict__ bih,
                                               const float* __restrict__ bgate,
                                               const float* __restrict__ bhh,
                                               float* __restrict__ xsA,
                                               float* __restrict__ xsB)
{
    size_t idx = blockIdx.x;
    const __half* col = XT + idx * BSZ;
    int tid = threadIdx.x, lane = tid & 31, wid = tid >> 5;
    float s = 0.f, q = 0.f;
    for (int i = tid; i < BSZ; i += 256) {
        float v = __half2float(col[i]); s += v; q += v * v;
    }
    __shared__ float wb[8][3];
#pragma unroll
    for (int o = 16; o > 0; o >>= 1) {
        s += __shfl_down_sync(0xffffffffu, s, o);
        q += __shfl_down_sync(0xffffffffu, q, o);
    }
    if (lane == 0) { wb[wid][0] = s; wb[wid][1] = q; }
    __syncthreads();
    if (tid == 0) {
        float S = 0.f, Q = 0.f;
        for (int w = 0; w < 8; w++) { S += wb[w][0]; Q += wb[w][1]; }
        float m = S * (1.f / BSZ);
        float var = Q * (1.f / BSZ) - m * m;
        float r = rsqrtf(var + EPS_);
        int n = (int)(idx % G4_);
        xsA[idx] = gih[n] * r;
        xsB[idx] = bih[n] - gih[n] * r * m + bgate[n] + bhh[n];
    }
}

// ---------------- persistent fused BN-LSTM layer (fp16 XT, fp16 h) ----------------
__global__ __launch_bounds__(NTHR, 1) void bnlstm_layer(
    const __half* __restrict__ XT,
    const float* __restrict__ xsA,
    const float* __restrict__ xsB,
    const float* __restrict__ Whh,
    const float* __restrict__ ghh,
    const float* __restrict__ gc,
    const float* __restrict__ bc,
    float* __restrict__ hsOut,
    __half* __restrict__ h16)
{
    const int j = blockIdx.x;
    const int tid = threadIdx.x;
    const int lane = tid & 31, wid = tid >> 5;
    const int b0 = tid * 2;

    __shared__ float4 WhhS4[128];
    __shared__ float red[16][8];
    __shared__ float stat[8];

    {
        float* WhhS = (float*)WhhS4;
        WhhS[tid] = Whh[(size_t)(tid >> 2) * G4_ + j + H_ * (tid & 3)];
    }
    float ghq[4];
#pragma unroll
    for (int q = 0; q < 4; q++) ghq[q] = ghh[j + H_ * q];
    const float gcj = gc[j], bcj = bc[j];
    __syncthreads();

    float cc0 = 0.f, cc1 = 0.f;
    unsigned barTarget = 0;

    for (int t = 0; t < T_; t++) {
        const __half* Xt = XT + (size_t)t * G4_ * BSZ;
        float2 xv[4];
        float xa[4], xb[4];
#pragma unroll
        for (int q = 0; q < 4; q++) {
            const int n = j + H_ * q;
            xv[q] = __half22float2(*(const __half2*)&Xt[(size_t)n * BSZ + b0]);
            xa[q] = xsA[t * G4_ + n];
            xb[q] = xsB[t * G4_ + n];
        }

        float gate[4][2];
        if (t == 0) {
#pragma unroll
            for (int q = 0; q < 4; q++) {
                gate[q][0] = fmaf(xa[q], xv[q].x, xb[q]);
                gate[q][1] = fmaf(xa[q], xv[q].y, xb[q]);
            }
        } else {
            const __half* hp = h16 + (size_t)((t - 1) & 1) * H_ * BSZ + b0;
            ull aP01_0 = 0ull, aP23_0 = 0ull;
            ull aP01_1 = 0ull, aP23_1 = 0ull;
#pragma unroll 8
            for (int k = 0; k < H_; k++) {
                const __half2 hraw = *(const __half2*)&hp[(size_t)k * BSZ];
                const float2 hf = __half22float2(hraw);
                const float4 wv = WhhS4[k];
                const ull w01 = pack2(wv.x, wv.y);
                const ull w23 = pack2(wv.z, wv.w);
                const ull h0d = pack2(hf.x, hf.x);
                const ull h1d = pack2(hf.y, hf.y);
                fma2(aP01_0, w01, h0d);
                fma2(aP23_0, w23, h0d);
                fma2(aP01_1, w01, h1d);
                fma2(aP23_1, w23, h1d);
            }
            float acc[4][2];
            unpack2(aP01_0, acc[0][0], acc[1][0]);
            unpack2(aP23_0, acc[2][0], acc[3][0]);
            unpack2(aP01_1, acc[0][1], acc[1][1]);
            unpack2(aP23_1, acc[2][1], acc[3][1]);

            float vals[8];
#pragma unroll
            for (int q = 0; q < 4; q++) {
                vals[q]     = acc[q][0] + acc[q][1];
                vals[4 + q] = acc[q][0]*acc[q][0] + acc[q][1]*acc[q][1];
            }
#pragma unroll
            for (int v = 0; v < 8; v++) {
                float x = vals[v];
#pragma unroll
                for (int o = 16; o > 0; o >>= 1) x += __shfl_down_sync(0xffffffffu, x, o);
                if (lane == 0) red[wid][v] = x;
            }
            __syncthreads();
            if (tid < 8) {
                float s = 0.f;
#pragma unroll
                for (int w = 0; w < 16; w++) s += red[w][tid];
                stat[tid] = s;
            }
            __syncthreads();
#pragma unroll
            for (int q = 0; q < 4; q++) {
                const float m   = stat[q] * (1.f / BSZ);
                const float var = stat[4 + q] * (1.f / BSZ) - m * m;
                const float gr  = ghq[q] * rsqrtf(var + EPS_);
                gate[q][0] = fmaf(xa[q], xv[q].x, xb[q]) + gr * (acc[q][0] - m);
                gate[q][1] = fmaf(xa[q], xv[q].y, xb[q]) + gr * (acc[q][1] - m);
            }
        }

        cc0 = sigm(gate[0][0]) * cc0 + sigm(gate[1][0]) * tanh_fast(gate[3][0]);
        cc1 = sigm(gate[0][1]) * cc1 + sigm(gate[1][1]) * tanh_fast(gate[3][1]);
        float cs = cc0 + cc1;
        float cq = cc0 * cc0 + cc1 * cc1;
#pragma unroll
        for (int o = 16; o > 0; o >>= 1) {
            cs += __shfl_down_sync(0xffffffffu, cs, o);
            cq += __shfl_down_sync(0xffffffffu, cq, o);
        }
        __syncthreads();
        if (lane == 0) { red[wid][0] = cs; red[wid][1] = cq; }
        __syncthreads();
        if (tid < 2) {
            float s = 0.f;
#pragma unroll
            for (int w = 0; w < 16; w++) s += red[w][tid];
            stat[tid] = s;
        }
        __syncthreads();

        const float mc = stat[0] * (1.f / BSZ);
        const float rc = rsqrtf(stat[1] * (1.f / BSZ) - mc * mc + EPS_);
        float2 hv;
        hv.x = sigm(gate[2][0]) * tanh_fast(fmaf(gcj * rc, cc0 - mc, bcj));
        hv.y = sigm(gate[2][1]) * tanh_fast(fmaf(gcj * rc, cc1 - mc, bcj));
        *(float2*)&hsOut[(size_t)t * H_ * BSZ + (size_t)j * BSZ + b0] = hv;
        __half2 hh = __floats2half2_rn(hv.x, hv.y);
        *(__half2*)&h16[(size_t)(t & 1) * H_ * BSZ + (size_t)j * BSZ + b0] = hh;

        if (t < T_ - 1) {
            barTarget += NBLK;
            if (tid == 0) {
                __threadfence();
                atomicAdd(&g_barArr, 1u);
                while (*((volatile unsigned*)&g_barArr) < barTarget) __nanosleep(64);
                __threadfence();
            }
            __syncthreads();
        }
    }
}

// ---------------- launch ----------------
extern "C" void kernel_launch(void* const* d_in, const int* in_sizes, int n_in,
                              void* d_out, int out_size)
{
    const float* seq  = (const float*)d_in[0];
    const float* Wih0 = (const float*)d_in[1];
    const float* Whh0 = (const float*)d_in[2];
    const float* b0   = (const float*)d_in[3];
    const float* gih0 = (const float*)d_in[4];
    const float* bih0 = (const float*)d_in[5];
    const float* ghh0 = (const float*)d_in[6];
    const float* bhh0 = (const float*)d_in[7];
    const float* gc0  = (const float*)d_in[8];
    const float* bc0  = (const float*)d_in[9];
    const float* Wih1 = (const float*)d_in[10];
    const float* Whh1 = (const float*)d_in[11];
    const float* b1   = (const float*)d_in[12];
    const float* gih1 = (const float*)d_in[13];
    const float* bih1 = (const float*)d_in[14];
    const float* ghh1 = (const float*)d_in[15];
    const float* bhh1 = (const float*)d_in[16];
    const float* gc1  = (const float*)d_in[17];
    const float* bc1  = (const float*)d_in[18];
    const float* fcw  = (const float*)d_in[19];
    const float* fcb  = (const float*)d_in[20];
    const float* decw = (const float*)d_in[21];
    const float* decb = (const float*)d_in[22];
    float* out = (float*)d_out;
    (void)in_sizes; (void)n_in; (void)out_size;

    __half *XT, *xbk, *hbk, *Wt, *h16;
    float *hs0T, *hs1T, *xsA, *xsB, *embT;
    cudaGetSymbolAddress((void**)&XT,   g_XT);
    cudaGetSymbolAddress((void**)&xbk,  g_xbk);
    cudaGetSymbolAddress((void**)&hbk,  g_hbk);
    cudaGetSymbolAddress((void**)&Wt,   g_Wt);
    cudaGetSymbolAddress((void**)&h16,  g_h16);
    cudaGetSymbolAddress((void**)&hs0T, g_hs0T);
    cudaGetSymbolAddress((void**)&hs1T, g_hs1T);
    cudaGetSymbolAddress((void**)&xsA,  g_xsA);
    cudaGetSymbolAddress((void**)&xsB,  g_xsB);
    cudaGetSymbolAddress((void**)&embT, g_embT);

    const int HMMA_SMEM = 2 * 128 * SROW * (int)sizeof(__half);  // ~68 KB
    static int attr_set = 0;
    if (!attr_set) {
        cudaFuncSetAttribute(hmma_gemm, cudaFuncAttributeMaxDynamicSharedMemorySize, HMMA_SMEM);
        attr_set = 1;
    }

    // ---- layer 0 ----
    x_to_bk<<<dim3(BSZ * 128 / 256, T_), 256>>>(seq, xbk);
    w_to_t<<<G4_ * 128 / 256, 256>>>(Wih0, Wt, IN_);
    hmma_gemm<<<dim3(BSZ / 128, G4_ / 128, T_), 256, HMMA_SMEM>>>(Wt, xbk, XT);
    x_stats<<<T_ * G4_, 256>>>(XT, gih0, bih0, b0, bhh0, xsA, xsB);
    reset_bar_k<<<1, 1>>>();
    bnlstm_layer<<<NBLK, NTHR>>>(XT, xsA, xsB, Whh0, ghh0, gc0, bc0, hs0T, h16);

    // ---- layer 1 ----
    h_to_bk<<<dim3(BSZ / 32, H_ / 32, T_), 256>>>(hs0T, hbk);
    w_to_t<<<G4_ * 128 / 256, 256>>>(Wih1, Wt, H_);
    hmma_gemm<<<dim3(BSZ / 128, G4_ / 128, T_), 256, HMMA_SMEM>>>(Wt, hbk, XT);
    x_stats<<<T_ * G4_, 256>>>(XT, gih1, bih1, b1, bhh1, xsA, xsB);
    reset_bar_k<<<1, 1>>>();
    bnlstm_layer<<<NBLK, NTHR>>>(XT, xsA, xsB, Whh1, ghh1, gc1, bc1, hs1T, h16);

    // ---- head ----
    tn_gemm128<<<dim3(BSZ / 128, OUT_ / 128, 1), 256>>>(fcw, hs1T + (size_t)(T_ - 1) * H_ * BSZ,
                                                        embT, H_, OUT_, BSZ,
                                                        0, 0, fcb, nullptr);
    tn_gemm128<<<dim3(MDEC / 128, BSZ / 128, 1), 256>>>(embT, decw, out, OUT_, BSZ, MDEC,
                                                        0, 0, nullptr, decb);
}

// round 8
// speedup vs baseline: 1.6166x; 1.0626x over previous
#include <cuda_runtime.h>
#include <cuda_fp16.h>
#include <math.h>
#include <stdint.h>

#define T_    128
#define BSZ   1024
#define IN_   75
#define H_    128
#define G4_   512
#define OUT_  256
#define MDEC  (128*75)
#define EPS_  1e-5f
#define NBLK  128
#define NTHR  512

typedef unsigned long long ull;

// ---------------- device scratch ----------------
__device__ __half g_XT  [(size_t)T_*G4_*BSZ];  // (T, 4H, B) fp16 gate pre-activations
__device__ __half g_xbk [(size_t)T_*BSZ*128];  // (T, B, 128) fp16 padded input, k-contig
__device__ __half g_hbk [(size_t)T_*BSZ*128];  // (T, B, 128) fp16 hs0 transposed, k-contig
__device__ __half g_Wt  [(size_t)G4_*128];     // (512, 128) fp16 W^T k-contig
__device__ float  g_hs0T[(size_t)T_*H_*BSZ];
__device__ float  g_hs1T[(size_t)T_*H_*BSZ];
__device__ __half g_h16 [(size_t)2*H_*BSZ];    // ping-pong fp16 recurrent h
__device__ float  g_xsA [(size_t)T_*G4_];
__device__ float  g_xsB [(size_t)T_*G4_];
__device__ float  g_embT[(size_t)OUT_*BSZ];
__device__ unsigned g_barArr;

__global__ void reset_bar_k() { g_barArr = 0u; }

__device__ __forceinline__ float tanh_fast(float x) {
    float y; asm("tanh.approx.f32 %0, %1;" : "=f"(y) : "f"(x)); return y;
}
__device__ __forceinline__ float sigm(float x) {
    return fmaf(0.5f, tanh_fast(0.5f * x), 0.5f);
}
__device__ __forceinline__ ull pack2(float lo, float hi) {
    ull r; asm("mov.b64 %0, {%1, %2};" : "=l"(r) : "f"(lo), "f"(hi)); return r;
}
__device__ __forceinline__ void unpack2(ull v, float& lo, float& hi) {
    asm("mov.b64 {%0, %1}, %2;" : "=f"(lo), "=f"(hi) : "l"(v));
}
__device__ __forceinline__ void fma2(ull& d, ull a, ull b) {
    asm("fma.rn.f32x2 %0, %1, %2, %0;" : "+l"(d) : "l"(a), "l"(b));
}
__device__ __forceinline__ void mma16816(float* c, const uint32_t* a, const uint32_t* b) {
    asm volatile(
        "mma.sync.aligned.m16n8k16.row.col.f32.f16.f16.f32 "
        "{%0,%1,%2,%3}, {%4,%5,%6,%7}, {%8,%9}, {%0,%1,%2,%3};"
        : "+f"(c[0]), "+f"(c[1]), "+f"(c[2]), "+f"(c[3])
        : "r"(a[0]), "r"(a[1]), "r"(a[2]), "r"(a[3]), "r"(b[0]), "r"(b[1]));
}

// ================= HMMA fp16 FF GEMM =================
// XT[t][n][b] = sum_k Wt[n][k] * Xbk[t][b][k]
#define SROW 136

__global__ __launch_bounds__(256) void hmma_gemm(
    const __half* __restrict__ Wt,
    const __half* __restrict__ Xbk,
    __half* __restrict__ XT)
{
    extern __shared__ __half sm[];
    __half* As = sm;
    __half* Bs = sm + 128 * SROW;

    const int t  = blockIdx.z;
    const int n0 = blockIdx.y * 128;
    const int b0 = blockIdx.x * 128;
    const int tid = threadIdx.x;
    const int wid = tid >> 5, lane = tid & 31;
    const int wm = wid >> 1;
    const int wn = wid & 1;

    {
        const float4* Ag = (const float4*)(Wt + (size_t)n0 * 128);
        const float4* Bg = (const float4*)(Xbk + ((size_t)t * BSZ + b0) * 128);
#pragma unroll
        for (int it = 0; it < 8; it++) {
            int i = tid + 256 * it;
            int r = i >> 4, c8 = (i & 15) * 8;
            *(float4*)&As[r * SROW + c8] = Ag[i];
            *(float4*)&Bs[r * SROW + c8] = Bg[i];
        }
    }
    __syncthreads();

    float acc[2][8][4];
#pragma unroll
    for (int mt = 0; mt < 2; mt++)
#pragma unroll
        for (int nt = 0; nt < 8; nt++)
#pragma unroll
            for (int e = 0; e < 4; e++) acc[mt][nt][e] = 0.f;

    const int fr = lane >> 2;
    const int kp = (lane & 3) * 2;

#pragma unroll
    for (int ks = 0; ks < 8; ks++) {
        const int k0 = ks * 16;
        uint32_t a[2][4];
#pragma unroll
        for (int mt = 0; mt < 2; mt++) {
            const int mr = wm * 32 + mt * 16;
            a[mt][0] = *(const uint32_t*)&As[(mr + fr)     * SROW + k0 + kp];
            a[mt][1] = *(const uint32_t*)&As[(mr + fr + 8) * SROW + k0 + kp];
            a[mt][2] = *(const uint32_t*)&As[(mr + fr)     * SROW + k0 + kp + 8];
            a[mt][3] = *(const uint32_t*)&As[(mr + fr + 8) * SROW + k0 + kp + 8];
        }
#pragma unroll
        for (int nt = 0; nt < 8; nt++) {
            const int bc = wn * 64 + nt * 8 + fr;
            uint32_t b[2];
            b[0] = *(const uint32_t*)&Bs[bc * SROW + k0 + kp];
            b[1] = *(const uint32_t*)&Bs[bc * SROW + k0 + kp + 8];
            mma16816(acc[0][nt], a[0], b);
            mma16816(acc[1][nt], a[1], b);
        }
    }

#pragma unroll
    for (int mt = 0; mt < 2; mt++) {
        const int n = n0 + wm * 32 + mt * 16 + fr;
        __half* R0 = XT + ((size_t)t * G4_ + n)     * BSZ + b0;
        __half* R1 = XT + ((size_t)t * G4_ + n + 8) * BSZ + b0;
#pragma unroll
        for (int nt = 0; nt < 8; nt++) {
            const int bcol = wn * 64 + nt * 8 + (lane & 3) * 2;
            *(__half2*)&R0[bcol] = __floats2half2_rn(acc[mt][nt][0], acc[mt][nt][1]);
            *(__half2*)&R1[bcol] = __floats2half2_rn(acc[mt][nt][2], acc[mt][nt][3]);
        }
    }
}

// ---------------- operand prep kernels ----------------
__global__ __launch_bounds__(256) void w_to_t(const float* __restrict__ W,
                                              __half* __restrict__ Wt, int K)
{
    int i = blockIdx.x * 256 + threadIdx.x;
    int n = i >> 7, k = i & 127;
    Wt[i] = __float2half(k < K ? W[(size_t)k * G4_ + n] : 0.f);
}

__global__ __launch_bounds__(256) void x_to_bk(const float* __restrict__ seq,
                                               __half* __restrict__ xbk)
{
    int t = blockIdx.y;
    size_t i = (size_t)blockIdx.x * 256 + threadIdx.x;
    int b = (int)(i >> 7), k = (int)(i & 127);
    float v = (k < IN_) ? seq[((size_t)b * T_ + t) * IN_ + k] : 0.f;
    xbk[(size_t)t * BSZ * 128 + i] = __float2half(v);
}

__global__ __launch_bounds__(256) void h_to_bk(const float* __restrict__ hsT,
                                               __half* __restrict__ hbk)
{
    int t = blockIdx.z;
    int h0 = blockIdx.y * 32;
    int b0 = blockIdx.x * 32;
    __shared__ float sm[32][33];
    int tid = threadIdx.x;
    int lx = tid & 31, ly = tid >> 5;
#pragma unroll
    for (int i = 0; i < 4; i++) {
        int h = h0 + ly + i * 8;
        sm[ly + i * 8][lx] = hsT[((size_t)t * H_ + h) * BSZ + b0 + lx];
    }
    __syncthreads();
#pragma unroll
    for (int i = 0; i < 4; i++) {
        int b = b0 + ly + i * 8;
        hbk[((size_t)t * BSZ + b) * 128 + h0 + lx] = __float2half(sm[lx][ly + i * 8]);
    }
}

// ---------------- TN SGEMM 128x128 FFMA2 (fc + decoder, fp32) ----------------
__global__ __launch_bounds__(256) void tn_gemm128(const float* __restrict__ W,
                                                  const float* __restrict__ A,
                                                  float* __restrict__ C,
                                                  int K, int N, int Bd,
                                                  long long strideA, long long strideC,
                                                  const float* __restrict__ bias_n,
                                                  const float* __restrict__ bias_b)
{
    A += (size_t)blockIdx.z * strideA;
    C += (size_t)blockIdx.z * strideC;
    const int n0 = blockIdx.y * 128;
    const int b0 = blockIdx.x * 128;

    __shared__ float Ws[16][128];
    __shared__ float As[16][128];

    const int tid = threadIdx.x;
    const int lr = tid / 32;
    const int lc = (tid % 32) * 4;
    const int tx = tid % 16;
    const int ty = tid / 16;

    ull accP[8][4];
#pragma unroll
    for (int i = 0; i < 8; i++)
#pragma unroll
        for (int jp = 0; jp < 4; jp++) accP[i][jp] = 0ull;

    for (int k0 = 0; k0 < K; k0 += 16) {
#pragma unroll
        for (int rr = 0; rr < 2; rr++) {
            const int krow = k0 + lr + rr * 8;
            float4 wv = make_float4(0.f, 0.f, 0.f, 0.f);
            float4 av = make_float4(0.f, 0.f, 0.f, 0.f);
            if (krow < K) {
                wv = *(const float4*)&W[(size_t)krow * N  + n0 + lc];
                av = *(const float4*)&A[(size_t)krow * Bd + b0 + lc];
            }
            *(float4*)&Ws[lr + rr * 8][lc] = wv;
            *(float4*)&As[lr + rr * 8][lc] = av;
        }
        __syncthreads();
#pragma unroll
        for (int kk = 0; kk < 16; kk++) {
            float a[8];
            float4 bq0 = *(const float4*)&As[kk][tx * 8];
            float4 bq1 = *(const float4*)&As[kk][tx * 8 + 4];
            *(float4*)&a[0] = *(const float4*)&Ws[kk][ty * 8];
            *(float4*)&a[4] = *(const float4*)&Ws[kk][ty * 8 + 4];
            ull bp[4];
            bp[0] = pack2(bq0.x, bq0.y);
            bp[1] = pack2(bq0.z, bq0.w);
            bp[2] = pack2(bq1.x, bq1.y);
            bp[3] = pack2(bq1.z, bq1.w);
#pragma unroll
            for (int i = 0; i < 8; i++) {
                const ull ad = pack2(a[i], a[i]);
#pragma unroll
                for (int jp = 0; jp < 4; jp++) fma2(accP[i][jp], ad, bp[jp]);
            }
        }
        __syncthreads();
    }

#pragma unroll
    for (int i = 0; i < 8; i++) {
        const int n = n0 + ty * 8 + i;
        const float bn = bias_n ? bias_n[n] : 0.f;
        float v[8];
#pragma unroll
        for (int jp = 0; jp < 4; jp++) unpack2(accP[i][jp], v[2 * jp], v[2 * jp + 1]);
        float4 o0, o1;
        o0.x = v[0] + bn; o0.y = v[1] + bn; o0.z = v[2] + bn; o0.w = v[3] + bn;
        o1.x = v[4] + bn; o1.y = v[5] + bn; o1.z = v[6] + bn; o1.w = v[7] + bn;
        if (bias_b) {
            const int bb = b0 + tx * 8;
            o0.x += bias_b[bb + 0]; o0.y += bias_b[bb + 1];
            o0.z += bias_b[bb + 2]; o0.w += bias_b[bb + 3];
            o1.x += bias_b[bb + 4]; o1.y += bias_b[bb + 5];
            o1.z += bias_b[bb + 6]; o1.w += bias_b[bb + 7];
        }
        *(float4*)&C[(size_t)n * Bd + b0 + tx * 8]     = o0;
        *(float4*)&C[(size_t)n * Bd + b0 + tx * 8 + 4] = o1;
    }
}

// ---------------- per-(t,n) BN stats: one WARP per column, uint4 loads ----------------
__global__ __launch_bounds__(256) void x_stats(const __half* __restrict__ XT,
                                               const float* __restrict__ gih,
                                               const float* __restrict__ bih,
                                               const float* __restrict__ bgate,
                                               const float* __restrict__ bhh,
                                               float* __restrict__ xsA,
                                               float* __restrict__ xsB)
{
    const int wid = threadIdx.x >> 5, lane = threadIdx.x & 31;
    const size_t idx = (size_t)blockIdx.x * 8 + wid;       // column (t*512+n)
    const uint4* col = (const uint4*)(XT + idx * BSZ);      // 128 x uint4
    float s = 0.f, q = 0.f;
#pragma unroll
    for (int i = 0; i < 4; i++) {
        uint4 v = col[lane + 32 * i];
        const __half2* hp = (const __half2*)&v;
#pragma unroll
        for (int j = 0; j < 4; j++) {
            float2 f = __half22float2(hp[j]);
            s += f.x + f.y;
            q += f.x * f.x + f.y * f.y;
        }
    }
#pragma unroll
    for (int o = 16; o > 0; o >>= 1) {
        s += __shfl_down_sync(0xffffffffu, s, o);
        q += __shfl_down_sync(0xffffffffu, q, o);
    }
    if (lane == 0) {
        float m = s * (1.f / BSZ);
        float var = q * (1.f / BSZ) - m * m;
        float r = rsqrtf(var + EPS_);
        int n = (int)(idx & (G4_ - 1));
        xsA[idx] = gih[n] * r;
        xsB[idx] = bih[n] - gih[n] * r * m + bgate[n] + bhh[n];
    }
}

// ---------------- persistent fused BN-LSTM layer (prefetch over barrier) ----------------
__global__ __launch_bounds__(NTHR, 1) void bnlstm_layer(
    const __half* __restrict__ XT,
    const float* __restrict__ xsA,
    const float* __restrict__ xsB,
    const float* __restrict__ Whh,
    const float* __restrict__ ghh,
    const float* __restrict__ gc,
    const float* __restrict__ bc,
    float* __restrict__ hsOut,
    __half* __restrict__ h16)
{
    const int j = blockIdx.x;
    const int tid = threadIdx.x;
    const int lane = tid & 31, wid = tid >> 5;
    const int b0 = tid * 2;

    __shared__ float4 WhhS4[128];
    __shared__ float red[16][8];
    __shared__ float stat[8];

    {
        float* WhhS = (float*)WhhS4;
        WhhS[tid] = Whh[(size_t)(tid >> 2) * G4_ + j + H_ * (tid & 3)];
    }
    float ghq[4];
#pragma unroll
    for (int q = 0; q < 4; q++) ghq[q] = ghh[j + H_ * q];
    const float gcj = gc[j], bcj = bc[j];
    __syncthreads();

    float cc0 = 0.f, cc1 = 0.f;
    unsigned barTarget = 0;

    // prefetch registers for x-side of the CURRENT step
    float2 xv[4];
    float xa[4], xb[4];
#pragma unroll
    for (int q = 0; q < 4; q++) {
        const int n = j + H_ * q;
        xv[q] = __half22float2(*(const __half2*)&XT[(size_t)n * BSZ + b0]);
        xa[q] = xsA[n];
        xb[q] = xsB[n];
    }

    for (int t = 0; t < T_; t++) {
        float gate[4][2];
        if (t == 0) {
#pragma unroll
            for (int q = 0; q < 4; q++) {
                gate[q][0] = fmaf(xa[q], xv[q].x, xb[q]);
                gate[q][1] = fmaf(xa[q], xv[q].y, xb[q]);
            }
        } else {
            const __half* hp = h16 + (size_t)((t - 1) & 1) * H_ * BSZ + b0;
            ull aP01_0 = 0ull, aP23_0 = 0ull;
            ull aP01_1 = 0ull, aP23_1 = 0ull;
#pragma unroll 8
            for (int k = 0; k < H_; k++) {
                const __half2 hraw = *(const __half2*)&hp[(size_t)k * BSZ];
                const float2 hf = __half22float2(hraw);
                const float4 wv = WhhS4[k];
                const ull w01 = pack2(wv.x, wv.y);
                const ull w23 = pack2(wv.z, wv.w);
                const ull h0d = pack2(hf.x, hf.x);
                const ull h1d = pack2(hf.y, hf.y);
                fma2(aP01_0, w01, h0d);
                fma2(aP23_0, w23, h0d);
                fma2(aP01_1, w01, h1d);
                fma2(aP23_1, w23, h1d);
            }
            float acc[4][2];
            unpack2(aP01_0, acc[0][0], acc[1][0]);
            unpack2(aP23_0, acc[2][0], acc[3][0]);
            unpack2(aP01_1, acc[0][1], acc[1][1]);
            unpack2(aP23_1, acc[2][1], acc[3][1]);

            float vals[8];
#pragma unroll
            for (int q = 0; q < 4; q++) {
                vals[q]     = acc[q][0] + acc[q][1];
                vals[4 + q] = acc[q][0]*acc[q][0] + acc[q][1]*acc[q][1];
            }
#pragma unroll
            for (int v = 0; v < 8; v++) {
                float x = vals[v];
#pragma unroll
                for (int o = 16; o > 0; o >>= 1) x += __shfl_down_sync(0xffffffffu, x, o);
                if (lane == 0) red[wid][v] = x;
            }
            __syncthreads();
            if (tid < 8) {
                float s = 0.f;
#pragma unroll
                for (int w = 0; w < 16; w++) s += red[w][tid];
                stat[tid] = s;
            }
            __syncthreads();
#pragma unroll
            for (int q = 0; q < 4; q++) {
                const float m   = stat[q] * (1.f / BSZ);
                const float var = stat[4 + q] * (1.f / BSZ) - m * m;
                const float gr  = ghq[q] * rsqrtf(var + EPS_);
                gate[q][0] = fmaf(xa[q], xv[q].x, xb[q]) + gr * (acc[q][0] - m);
                gate[q][1] = fmaf(xa[q], xv[q].y, xb[q]) + gr * (acc[q][1] - m);
            }
        }

        cc0 = sigm(gate[0][0]) * cc0 + sigm(gate[1][0]) * tanh_fast(gate[3][0]);
        cc1 = sigm(gate[0][1]) * cc1 + sigm(gate[1][1]) * tanh_fast(gate[3][1]);
        float cs = cc0 + cc1;
        float cq = cc0 * cc0 + cc1 * cc1;
#pragma unroll
        for (int o = 16; o > 0; o >>= 1) {
            cs += __shfl_down_sync(0xffffffffu, cs, o);
            cq += __shfl_down_sync(0xffffffffu, cq, o);
        }
        __syncthreads();
        if (lane == 0) { red[wid][0] = cs; red[wid][1] = cq; }
        __syncthreads();
        if (tid < 2) {
            float s = 0.f;
#pragma unroll
            for (int w = 0; w < 16; w++) s += red[w][tid];
            stat[tid] = s;
        }
        __syncthreads();

        const float mc = stat[0] * (1.f / BSZ);
        const float rc = rsqrtf(stat[1] * (1.f / BSZ) - mc * mc + EPS_);
        float2 hv;
        hv.x = sigm(gate[2][0]) * tanh_fast(fmaf(gcj * rc, cc0 - mc, bcj));
        hv.y = sigm(gate[2][1]) * tanh_fast(fmaf(gcj * rc, cc1 - mc, bcj));
        *(float2*)&hsOut[(size_t)t * H_ * BSZ + (size_t)j * BSZ + b0] = hv;
        __half2 hh = __floats2half2_rn(hv.x, hv.y);
        *(__half2*)&h16[(size_t)(t & 1) * H_ * BSZ + (size_t)j * BSZ + b0] = hh;

        if (t < T_ - 1) {
            // prefetch t+1's x-side BEFORE the barrier (read-only data; overlaps wait)
            const __half* XtN = XT + (size_t)(t + 1) * G4_ * BSZ;
            const float* xsAN = xsA + (size_t)(t + 1) * G4_;
            const float* xsBN = xsB + (size_t)(t + 1) * G4_;
#pragma unroll
            for (int q = 0; q < 4; q++) {
                const int n = j + H_ * q;
                xv[q] = __half22float2(*(const __half2*)&XtN[(size_t)n * BSZ + b0]);
                xa[q] = xsAN[n];
                xb[q] = xsBN[n];
            }
            barTarget += NBLK;
            if (tid == 0) {
                __threadfence();
                atomicAdd(&g_barArr, 1u);
                while (*((volatile unsigned*)&g_barArr) < barTarget) __nanosleep(64);
                __threadfence();
            }
            __syncthreads();
        }
    }
}

// ---------------- launch ----------------
extern "C" void kernel_launch(void* const* d_in, const int* in_sizes, int n_in,
                              void* d_out, int out_size)
{
    const float* seq  = (const float*)d_in[0];
    const float* Wih0 = (const float*)d_in[1];
    const float* Whh0 = (const float*)d_in[2];
    const float* b0   = (const float*)d_in[3];
    const float* gih0 = (const float*)d_in[4];
    const float* bih0 = (const float*)d_in[5];
    const float* ghh0 = (const float*)d_in[6];
    const float* bhh0 = (const float*)d_in[7];
    const float* gc0  = (const float*)d_in[8];
    const float* bc0  = (const float*)d_in[9];
    const float* Wih1 = (const float*)d_in[10];
    const float* Whh1 = (const float*)d_in[11];
    const float* b1   = (const float*)d_in[12];
    const float* gih1 = (const float*)d_in[13];
    const float* bih1 = (const float*)d_in[14];
    const float* ghh1 = (const float*)d_in[15];
    const float* bhh1 = (const float*)d_in[16];
    const float* gc1  = (const float*)d_in[17];
    const float* bc1  = (const float*)d_in[18];
    const float* fcw  = (const float*)d_in[19];
    const float* fcb  = (const float*)d_in[20];
    const float* decw = (const float*)d_in[21];
    const float* decb = (const float*)d_in[22];
    float* out = (float*)d_out;
    (void)in_sizes; (void)n_in; (void)out_size;

    __half *XT, *xbk, *hbk, *Wt, *h16;
    float *hs0T, *hs1T, *xsA, *xsB, *embT;
    cudaGetSymbolAddress((void**)&XT,   g_XT);
    cudaGetSymbolAddress((void**)&xbk,  g_xbk);
    cudaGetSymbolAddress((void**)&hbk,  g_hbk);
    cudaGetSymbolAddress((void**)&Wt,   g_Wt);
    cudaGetSymbolAddress((void**)&h16,  g_h16);
    cudaGetSymbolAddress((void**)&hs0T, g_hs0T);
    cudaGetSymbolAddress((void**)&hs1T, g_hs1T);
    cudaGetSymbolAddress((void**)&xsA,  g_xsA);
    cudaGetSymbolAddress((void**)&xsB,  g_xsB);
    cudaGetSymbolAddress((void**)&embT, g_embT);

    const int HMMA_SMEM = 2 * 128 * SROW * (int)sizeof(__half);
    static int attr_set = 0;
    if (!attr_set) {
        cudaFuncSetAttribute(hmma_gemm, cudaFuncAttributeMaxDynamicSharedMemorySize, HMMA_SMEM);
        attr_set = 1;
    }

    // ---- layer 0 ----
    x_to_bk<<<dim3(BSZ * 128 / 256, T_), 256>>>(seq, xbk);
    w_to_t<<<G4_ * 128 / 256, 256>>>(Wih0, Wt, IN_);
    hmma_gemm<<<dim3(BSZ / 128, G4_ / 128, T_), 256, HMMA_SMEM>>>(Wt, xbk, XT);
    x_stats<<<T_ * G4_ / 8, 256>>>(XT, gih0, bih0, b0, bhh0, xsA, xsB);
    reset_bar_k<<<1, 1>>>();
    bnlstm_layer<<<NBLK, NTHR>>>(XT, xsA, xsB, Whh0, ghh0, gc0, bc0, hs0T, h16);

    // ---- layer 1 ----
    h_to_bk<<<dim3(BSZ / 32, H_ / 32, T_), 256>>>(hs0T, hbk);
    w_to_t<<<G4_ * 128 / 256, 256>>>(Wih1, Wt, H_);
    hmma_gemm<<<dim3(BSZ / 128, G4_ / 128, T_), 256, HMMA_SMEM>>>(Wt, hbk, XT);
    x_stats<<<T_ * G4_ / 8, 256>>>(XT, gih1, bih1, b1, bhh1, xsA, xsB);
    reset_bar_k<<<1, 1>>>();
    bnlstm_layer<<<NBLK, NTHR>>>(XT, xsA, xsB, Whh1, ghh1, gc1, bc1, hs1T, h16);

    // ---- head ----
    tn_gemm128<<<dim3(BSZ / 128, OUT_ / 128, 1), 256>>>(fcw, hs1T + (size_t)(T_ - 1) * H_ * BSZ,
                                                        embT, H_, OUT_, BSZ,
                                                        0, 0, fcb, nullptr);
    tn_gemm128<<<dim3(MDEC / 128, BSZ / 128, 1), 256>>>(embT, decw, out, OUT_, BSZ, MDEC,
                                                        0, 0, nullptr, decb);
}